// round 5
// baseline (speedup 1.0000x reference)
#include <cuda_runtime.h>

// SNN XORNet, T=20 LIF. R4 was occupancy-capped (60 regs -> 8 CTA/SM, occ 39%, issue 61%).
// This round: 2 batch elements per thread (one f32x2 pair) to halve live state
// (~40-46 regs), __launch_bounds__(128,10) -> 48-reg cap -> 40 warps/SM (62.5%).
// 2x thread count also shrinks wave-quantization tail. IEEE op sequence per element
// unchanged from rounds 1-4 -> bit-identical output (rel_err 8.596e-4).

#define T_STEPS 20
#define BETA    0.9f
#define THR     1.0f

typedef unsigned long long u64;

__device__ __forceinline__ u64 pack2(float lo, float hi) {
    u64 r; asm("mov.b64 %0, {%1, %2};" : "=l"(r) : "f"(lo), "f"(hi)); return r;
}
__device__ __forceinline__ void unpack2(u64 v, float& lo, float& hi) {
    asm("mov.b64 {%0, %1}, %2;" : "=f"(lo), "=f"(hi) : "l"(v));
}
__device__ __forceinline__ u64 fma2(u64 a, u64 b, u64 c) {
    u64 r; asm("fma.rn.f32x2 %0, %1, %2, %3;" : "=l"(r) : "l"(a), "l"(b), "l"(c)); return r;
}
__device__ __forceinline__ float fset_gt(float a, float b) {
    float r; asm("set.gt.f32.f32 %0, %1, %2;" : "=f"(r) : "f"(a), "f"(b)); return r;
}
__device__ __forceinline__ u64 spike2(u64 m) {
    float lo, hi; unpack2(m, lo, hi);
    return pack2(fset_gt(lo, THR), fset_gt(hi, THR));
}

__global__ __launch_bounds__(128, 10)
void snn_kernel(const float* __restrict__ x,
                const float* __restrict__ w1,   // [4,2]
                const float* __restrict__ w2,   // [1,4]
                float* __restrict__ out,        // [T, B]
                int B)
{
    const int tid = blockIdx.x * blockDim.x + threadIdx.x;
    const int i0  = tid * 2;                    // 2 batch elements = 1 f32x2 pair
    if (i0 >= B) return;

    float w1v[8];
#pragma unroll
    for (int k = 0; k < 8; k++) w1v[k] = __ldg(w1 + k);
    u64 w2p[4];
#pragma unroll
    for (int k = 0; k < 4; k++) { float w = __ldg(w2 + k); w2p[k] = pack2(w, w); }

    const u64 BETA2 = pack2(BETA, BETA);
    const u64 NEG1  = pack2(-1.f, -1.f);

    // x for 2 elements: 4 contiguous floats
    const float4 xa = *reinterpret_cast<const float4*>(x + 2 * (size_t)i0);
    const float xe[2][2] = {{xa.x, xa.y}, {xa.z, xa.w}};

    // cur (timestep-invariant), packed: lane0=elem i0, lane1=elem i0+1 (same math as R1)
    u64 cur2[4];
#pragma unroll
    for (int h = 0; h < 4; h++) {
        float c0 = fmaf(xe[0][1], w1v[2*h+1], xe[0][0] * w1v[2*h]);
        float c1 = fmaf(xe[1][1], w1v[2*h+1], xe[1][0] * w1v[2*h]);
        cur2[h] = pack2(c0, c1);
    }

    // Rotated state: pre-spike membranes. t=0: m1 = beta*0 + cur - 0 = cur (exact).
    u64 m1[4];
#pragma unroll
    for (int h = 0; h < 4; h++) m1[h] = cur2[h];
    u64 m2 = 0ull, s2 = 0ull;

    float* outp = out + i0;
    const size_t stride = (size_t)B;

#pragma unroll 1
    for (int t = 0; t < T_STEPS; t++) {
        u64 acc = 0ull;
        u64 s1[4];                        // body-local
#pragma unroll
        for (int h = 0; h < 4; h++) {
            s1[h] = spike2(m1[h]);                    // spk1_t = (m1_t > 1)
            acc = fma2(s1[h], w2p[h], acc);           // out_t += spk1*w2 (seq order)
        }
        m2 = fma2(BETA2, m2, acc);                    // beta*m2 + out
        m2 = fma2(s2, NEG1, m2);                      // - spk2_{t-1}
        s2 = spike2(m2);                              // spk2_t
        float lo, hi; unpack2(s2, lo, hi);
        *reinterpret_cast<float2*>(outp + (size_t)t * stride) = make_float2(lo, hi);
        // advance layer1: m1_{t+1} = beta*m1_t + cur - spk1_t
#pragma unroll
        for (int h = 0; h < 4; h++) {
            m1[h] = fma2(BETA2, m1[h], cur2[h]);
            m1[h] = fma2(s1[h], NEG1, m1[h]);
        }
    }
}

extern "C" void kernel_launch(void* const* d_in, const int* in_sizes, int n_in,
                              void* d_out, int out_size)
{
    const float* x  = (const float*)d_in[0];   // [B,2]
    const float* w1 = (const float*)d_in[1];   // [4,2]
    const float* w2 = (const float*)d_in[2];   // [1,4]
    float* out = (float*)d_out;                // [T,B,1]

    const int B = in_sizes[0] / 2;             // 1,048,576
    const int elems_per_thread = 2;
    const int nthreads = (B + elems_per_thread - 1) / elems_per_thread;
    const int block = 128;
    const int grid = (nthreads + block - 1) / block;

    snn_kernel<<<grid, block>>>(x, w1, w2, out, B);
}

// round 6
// speedup vs baseline: 1.1952x; 1.1952x over previous
#include <cuda_runtime.h>

// SNN XORNet, T=20 LIF. Evidence R3-R5: runtime ~ total issued instructions with an
// issue ceiling ~0.63/cyc/SMSP; occupancy irrelevant. This round: R3 structure
// (4 elems/thread, best inst/elem) + FULL unroll of the T loop (kills per-step
// IADD/ISETP/BRA and the >=10cyc BRA-taken bubble, ~12% fewer issued inst).
// IEEE op sequence per element unchanged from R1-R3 -> bit-identical output.

#define T_STEPS 20
#define BETA    0.9f
#define THR     1.0f

typedef unsigned long long u64;

__device__ __forceinline__ u64 pack2(float lo, float hi) {
    u64 r; asm("mov.b64 %0, {%1, %2};" : "=l"(r) : "f"(lo), "f"(hi)); return r;
}
__device__ __forceinline__ void unpack2(u64 v, float& lo, float& hi) {
    asm("mov.b64 {%0, %1}, %2;" : "=f"(lo), "=f"(hi) : "l"(v));
}
__device__ __forceinline__ u64 fma2(u64 a, u64 b, u64 c) {
    u64 r; asm("fma.rn.f32x2 %0, %1, %2, %3;" : "=l"(r) : "l"(a), "l"(b), "l"(c)); return r;
}
__device__ __forceinline__ float fset_gt(float a, float b) {
    float r; asm("set.gt.f32.f32 %0, %1, %2;" : "=f"(r) : "f"(a), "f"(b)); return r;
}
__device__ __forceinline__ u64 spike2(u64 m) {
    float lo, hi; unpack2(m, lo, hi);
    return pack2(fset_gt(lo, THR), fset_gt(hi, THR));
}

__global__ __launch_bounds__(128)
void snn_kernel(const float* __restrict__ x,
                const float* __restrict__ w1,   // [4,2]
                const float* __restrict__ w2,   // [1,4]
                float* __restrict__ out,        // [T, B]
                int B)
{
    const int tid = blockIdx.x * blockDim.x + threadIdx.x;
    const int i0  = tid * 4;                    // 4 batch elements = 2 f32x2 pairs
    if (i0 >= B) return;

    float w1v[8];
#pragma unroll
    for (int k = 0; k < 8; k++) w1v[k] = __ldg(w1 + k);
    u64 w2p[4];
#pragma unroll
    for (int k = 0; k < 4; k++) { float w = __ldg(w2 + k); w2p[k] = pack2(w, w); }

    const u64 BETA2 = pack2(BETA, BETA);
    const u64 NEG1  = pack2(-1.f, -1.f);

    const float4* xv = reinterpret_cast<const float4*>(x + 2 * (size_t)i0);
    float4 xa = xv[0];
    float4 xb = xv[1];
    float xe[4][2] = {{xa.x, xa.y}, {xa.z, xa.w}, {xb.x, xb.y}, {xb.z, xb.w}};

    // cur (timestep-invariant), packed per pair — same scalar math as R1.
    u64 cur2[2][4];
#pragma unroll
    for (int p = 0; p < 2; p++)
#pragma unroll
        for (int h = 0; h < 4; h++) {
            float c0 = fmaf(xe[2*p  ][1], w1v[2*h+1], xe[2*p  ][0] * w1v[2*h]);
            float c1 = fmaf(xe[2*p+1][1], w1v[2*h+1], xe[2*p+1][0] * w1v[2*h]);
            cur2[p][h] = pack2(c0, c1);
        }

    u64 m1[2][4], s1[2][4], m2[2], s2[2];
#pragma unroll
    for (int p = 0; p < 2; p++) {
#pragma unroll
        for (int h = 0; h < 4; h++) { m1[p][h] = 0ull; s1[p][h] = 0ull; }
        m2[p] = 0ull; s2[p] = 0ull;
    }

    float* outp = out + i0;
    const size_t stride = (size_t)B;

#pragma unroll   // FULL unroll: no loop inst, no BRA bubbles, const step offsets
    for (int t = 0; t < T_STEPS; t++) {
        float4 o;
        float* op = &o.x;
#pragma unroll
        for (int p = 0; p < 2; p++) {
            u64 acc = 0ull;
#pragma unroll
            for (int h = 0; h < 4; h++) {
                // m = beta*m + cur ; m -= s_prev (exact: s in {0,1})
                m1[p][h] = fma2(BETA2, m1[p][h], cur2[p][h]);
                m1[p][h] = fma2(s1[p][h], NEG1, m1[p][h]);
                s1[p][h] = spike2(m1[p][h]);           // spk1 = (m > 1)
                acc = fma2(s1[p][h], w2p[h], acc);     // out += spk1*w2 (seq order)
            }
            m2[p] = fma2(BETA2, m2[p], acc);
            m2[p] = fma2(s2[p], NEG1, m2[p]);
            s2[p] = spike2(m2[p]);
            float lo, hi; unpack2(s2[p], lo, hi);
            op[2*p]   = lo;
            op[2*p+1] = hi;
        }
        *reinterpret_cast<float4*>(outp + (size_t)t * stride) = o;  // coalesced 128b
    }
}

extern "C" void kernel_launch(void* const* d_in, const int* in_sizes, int n_in,
                              void* d_out, int out_size)
{
    const float* x  = (const float*)d_in[0];   // [B,2]
    const float* w1 = (const float*)d_in[1];   // [4,2]
    const float* w2 = (const float*)d_in[2];   // [1,4]
    float* out = (float*)d_out;                // [T,B,1]

    const int B = in_sizes[0] / 2;             // 1,048,576
    const int elems_per_thread = 4;
    const int nthreads = (B + elems_per_thread - 1) / elems_per_thread;
    const int block = 128;
    const int grid = (nthreads + block - 1) / block;

    snn_kernel<<<grid, block>>>(x, w1, w2, out, B);
}